// round 16
// baseline (speedup 1.0000x reference)
#include <cuda_runtime.h>
#include <cuda_bf16.h>
#include <math.h>
#include <stdint.h>

// Problem constants
constexpr int NN   = 20000;
constexpr int INC  = 512;
constexpr int C    = 128;
constexpr int H    = 4;
constexpr int HID  = H * C;        // 512
constexpr int NE   = 320000;
constexpr int ET   = NE + NN;      // 340000
constexpr int K1   = 1024;         // [hi|lo] split storage width
constexpr float NEG_SLOPE = 0.2f;
constexpr int SCAN_B = 512;
constexpr int SCAN_NB = (NN + SCAN_B - 1) / SCAN_B;  // 40

// ----------------------------------------------------------------------------
// Device-global scratch
// ----------------------------------------------------------------------------
__device__ __nv_bfloat16 g_xs[(size_t)NN * K1];
__device__ __nv_bfloat16 g_w1t[(size_t)HID * K1];
__device__ __nv_bfloat16 g_w2t[(size_t)C * K1];
__device__ float g_h1[(size_t)NN * HID];
__device__ __nv_bfloat16 g_out1s[(size_t)NN * K1];
__device__ float g_h2[(size_t)NN * C];
__device__ float g_als1[NN * H];
__device__ float g_ald1[NN * H];
__device__ float g_als2[NN];
__device__ float g_ald2[NN];
__device__ int   g_src[ET];
__device__ int   g_dst[ET];
__device__ int   g_deg[NN];
__device__ int   g_rowp[NN + 1];
__device__ int   g_cursor[NN];
__device__ int   g_csr_src[ET];
__device__ int   g_bsum[SCAN_NB];
__device__ int   g_boff[SCAN_NB];
__device__ int   g_is64;

// ----------------------------------------------------------------------------
// Edge-index dtype probe + decode + CSR build
// ----------------------------------------------------------------------------
__global__ void zero_init_kernel(int* __restrict__ p, int n) {
    int i = blockIdx.x * blockDim.x + threadIdx.x;
    if (i < n) p[i] = 0;
    if (i == 0) g_is64 = 1;
}
__global__ void det_kernel(const long long* __restrict__ p) {
    int i = blockIdx.x * blockDim.x + threadIdx.x;
    if (i < 65536) {
        unsigned long long v = (unsigned long long)p[i];
        if (v >= (unsigned long long)NN) g_is64 = 0;
    }
}
__global__ void prep_edges_kernel(const void* __restrict__ eib,
                                  int* __restrict__ src, int* __restrict__ dst,
                                  int* __restrict__ deg) {
    int e = blockIdx.x * blockDim.x + threadIdx.x;
    if (e >= ET) return;
    int s, d;
    if (e < NE) {
        if (g_is64) {
            const long long* p = (const long long*)eib;
            s = (int)p[e]; d = (int)p[NE + e];
        } else {
            const int* p = (const int*)eib;
            s = p[e]; d = p[NE + e];
        }
    } else {
        s = d = e - NE;
    }
    src[e] = s; dst[e] = d;
    atomicAdd(&deg[d], 1);
}
__global__ __launch_bounds__(SCAN_B) void scan1_kernel(const int* __restrict__ deg,
                                                       int* __restrict__ rowp,
                                                       int* __restrict__ bsum) {
    __shared__ int sh[SCAN_B];
    const int t = threadIdx.x;
    const int i = blockIdx.x * SCAN_B + t;
    int v = (i < NN) ? deg[i] : 0;
    sh[t] = v;
    __syncthreads();
    for (int off = 1; off < SCAN_B; off <<= 1) {
        int u = (t >= off) ? sh[t - off] : 0;
        __syncthreads();
        sh[t] += u;
        __syncthreads();
    }
    if (i < NN) rowp[i] = sh[t] - v;
    if (t == SCAN_B - 1) bsum[blockIdx.x] = sh[t];
}
__global__ void scan2_kernel(const int* __restrict__ bsum, int* __restrict__ boff) {
    int t = threadIdx.x;   // 64
    __shared__ int sh[64];
    sh[t] = (t < SCAN_NB) ? bsum[t] : 0;
    __syncthreads();
    for (int off = 1; off < 64; off <<= 1) {
        int u = (t >= off) ? sh[t - off] : 0;
        __syncthreads();
        sh[t] += u;
        __syncthreads();
    }
    if (t < SCAN_NB) boff[t] = sh[t] - bsum[t];
}
__global__ void scan3_kernel(int* __restrict__ rowp, const int* __restrict__ boff,
                             int* __restrict__ cursor) {
    int i = blockIdx.x * blockDim.x + threadIdx.x;
    if (i < NN) {
        int r = rowp[i] + boff[i / SCAN_B];
        rowp[i] = r;
        cursor[i] = r;
    }
    if (i == 0) rowp[NN] = ET;
}
__global__ void scatter_kernel(const int* __restrict__ src, const int* __restrict__ dst,
                               int* __restrict__ cursor, int* __restrict__ csr_src) {
    int e = blockIdx.x * blockDim.x + threadIdx.x;
    if (e >= ET) return;
    int p = atomicAdd(&cursor[dst[e]], 1);
    csr_src[p] = src[e];
}

// ----------------------------------------------------------------------------
// fp32 -> bf16 [hi|lo] split conversions (K1 = 1024 layout).
// ----------------------------------------------------------------------------
__global__ void conv_x_kernel(const float* __restrict__ x, __nv_bfloat16* __restrict__ xs) {
    int idx = blockIdx.x * blockDim.x + threadIdx.x;
    if (idx >= NN * 128) return;
    int row = idx >> 7, q = idx & 127;
    float4 v = *(const float4*)(x + (size_t)row * 512 + q * 4);
    __nv_bfloat16* o = xs + (size_t)row * K1 + q * 4;
    float vals[4] = { v.x, v.y, v.z, v.w };
#pragma unroll
    for (int j = 0; j < 4; j++) {
        __nv_bfloat16 hi = __float2bfloat16(vals[j]);
        __nv_bfloat16 lo = __float2bfloat16(vals[j] - __bfloat162float(hi));
        o[j] = hi; o[512 + j] = lo;
    }
}
__global__ void conv_w_kernel(const float* __restrict__ W, __nv_bfloat16* __restrict__ wt, int N) {
    int idx = blockIdx.x * blockDim.x + threadIdx.x;
    if (idx >= 512 * N) return;
    int k = idx / N, n = idx % N;
    float v = W[(size_t)k * N + n];
    __nv_bfloat16 hi = __float2bfloat16(v);
    __nv_bfloat16 lo = __float2bfloat16(v - __bfloat162float(hi));
    __nv_bfloat16* o = wt + (size_t)n * K1;
    o[k] = hi; o[512 + k] = lo;
}

// ----------------------------------------------------------------------------
// HMMA GEMM + fused attention epilogue — SMEM-cached tile reuse.
// Per kk (16 total, GK=32): load 4 tiles [Ahi|Alo|Bhi|Blo], run 3 sequential
// compute passes (Ahi*Bhi, Ahi*Blo, Alo*Bhi). -33% cp.async traffic,
// 16 barrier pairs; MMA/ldmatrix totals unchanged; no cross-pass registers.
// ----------------------------------------------------------------------------
constexpr int GK     = 32;
constexpr int LDT    = 40;                 // padded SMEM stride (bf16), 80 B
constexpr int NKK    = 16;
constexpr int NT     = 4;
constexpr int TILESZ = 128 * LDT * 2;      // 10240 B
constexpr int STG4   = 4 * TILESZ;         // 40960
constexpr int SMEM_G = 2 * STG4;           // 81920

__device__ __forceinline__ uint32_t smem_u32(const void* p) {
    uint32_t a;
    asm("{ .reg .u64 t; cvta.to.shared.u64 t, %1; cvt.u32.u64 %0, t; }"
        : "=r"(a) : "l"(p));
    return a;
}
__device__ __forceinline__ void cp16(uint32_t dst, const void* src, uint32_t sz) {
    asm volatile("cp.async.ca.shared.global [%0], [%1], 16, %2;"
                 :: "r"(dst), "l"(src), "r"(sz));
}
__device__ __forceinline__ void ldm_x4(uint32_t* r, uint32_t addr) {
    asm volatile("ldmatrix.sync.aligned.m8n8.x4.shared.b16 {%0,%1,%2,%3}, [%4];"
                 : "=r"(r[0]), "=r"(r[1]), "=r"(r[2]), "=r"(r[3]) : "r"(addr));
}
__device__ __forceinline__ void mma16816(float* d, const uint32_t* a, const uint32_t* b) {
    asm volatile(
        "mma.sync.aligned.m16n8k16.row.col.f32.bf16.bf16.f32 "
        "{%0,%1,%2,%3}, {%4,%5,%6,%7}, {%8,%9}, {%0,%1,%2,%3};"
        : "+f"(d[0]), "+f"(d[1]), "+f"(d[2]), "+f"(d[3])
        : "r"(a[0]), "r"(a[1]), "r"(a[2]), "r"(a[3]), "r"(b[0]), "r"(b[1]));
}

__global__ __launch_bounds__(256) void hmma_gemm_attn_kernel(
    const __nv_bfloat16* __restrict__ A, const __nv_bfloat16* __restrict__ B,
    float* __restrict__ Cm, int M, int Ntot,
    const float* __restrict__ a_src, const float* __restrict__ a_dst,
    float* __restrict__ als, float* __restrict__ ald, int HH)
{
    extern __shared__ __align__(128) char smem[];
    __shared__ float sals[128];
    __shared__ float sald[128];
    const uint32_t sbase = smem_u32(smem);

    const int tid  = threadIdx.x;
    const int wid  = tid >> 5;
    const int lane = tid & 31;
    const int warp_m = (wid >> 2) * 64;
    const int warp_n = (wid & 3) * 32;
    const int rowBase = blockIdx.y * 128;
    const int colBase = blockIdx.x * 128;
    const int head = blockIdx.x;

    if (tid < 128) { sals[tid] = 0.f; sald[tid] = 0.f; }

    float acc[4][NT][4];
#pragma unroll
    for (int i = 0; i < 4; i++)
#pragma unroll
        for (int j = 0; j < NT; j++)
#pragma unroll
            for (int q = 0; q < 4; q++) acc[i][j][q] = 0.f;

    // Stage: [Ahi | Alo | Bhi | Blo], each 128 rows x 32 bf16 (stride LDT)
    auto prefetch = [&](int kk, int buf) {
        uint32_t st = sbase + buf * STG4;
        const __nv_bfloat16* Ac = A + kk * GK;
        const __nv_bfloat16* Bc = B + kk * GK;
#pragma unroll
        for (int i = tid; i < 512; i += 256) {   // 128 rows x 4 16B-chunks
            int row = i >> 2, c16 = i & 3;
            uint32_t off = row * (LDT * 2) + c16 * 16;
            const size_t ga = (size_t)(rowBase + row) * K1 + c16 * 8;
            uint32_t asz = (rowBase + row < M) ? 16u : 0u;
            cp16(st + 0 * TILESZ + off, Ac + ga,       asz);
            cp16(st + 1 * TILESZ + off, Ac + 512 + ga, asz);
            const size_t gb = (size_t)(colBase + row) * K1 + c16 * 8;
            cp16(st + 2 * TILESZ + off, Bc + gb,       16u);
            cp16(st + 3 * TILESZ + off, Bc + 512 + gb, 16u);
        }
        asm volatile("cp.async.commit_group;");
    };

    // One compute pass over a (A-tile, B-tile) pair: 2 k16 slices.
    auto compute = [&](uint32_t ab, uint32_t bb) {
#pragma unroll
        for (int ks = 0; ks < 2; ks++) {
            uint32_t afrag[4][4];
#pragma unroll
            for (int i = 0; i < 4; i++) {
                int row = warp_m + i * 16 + (lane & 15);
                int col = ks * 16 + ((lane >> 4) << 3);
                ldm_x4(afrag[i], ab + row * (LDT * 2) + col * 2);
            }
            uint32_t bfrag[NT][2];
#pragma unroll
            for (int jj = 0; jj < NT / 2; jj++) {
                uint32_t r[4];
                int nrow = warp_n + jj * 16 + (lane & 7) + ((lane >> 4) << 3);
                int col  = ks * 16 + (((lane >> 3) & 1) << 3);
                ldm_x4(r, bb + nrow * (LDT * 2) + col * 2);
                bfrag[2 * jj + 0][0] = r[0]; bfrag[2 * jj + 0][1] = r[1];
                bfrag[2 * jj + 1][0] = r[2]; bfrag[2 * jj + 1][1] = r[3];
            }
#pragma unroll
            for (int i = 0; i < 4; i++)
#pragma unroll
                for (int j = 0; j < NT; j++)
                    mma16816(acc[i][j], afrag[i], bfrag[j]);
        }
    };

    prefetch(0, 0);

    for (int kk = 0; kk < NKK; kk++) {
        const int buf = kk & 1;
        if (kk + 1 < NKK) {
            prefetch(kk + 1, buf ^ 1);
            asm volatile("cp.async.wait_group 1;");
        } else {
            asm volatile("cp.async.wait_group 0;");
        }
        __syncthreads();

        uint32_t st  = sbase + buf * STG4;
        uint32_t ahb = st;
        uint32_t alb = st + TILESZ;
        uint32_t bhb = st + 2 * TILESZ;
        uint32_t blb = st + 3 * TILESZ;

        compute(ahb, bhb);   // Ahi * Bhi
        compute(ahb, blb);   // Ahi * Blo
        compute(alb, bhb);   // Alo * Bhi

        __syncthreads();
    }

    // Epilogue: store C tile + reduce attention dots into smem.
#pragma unroll
    for (int i = 0; i < 4; i++) {
#pragma unroll
        for (int half = 0; half < 2; half++) {
            int rloc = warp_m + i * 16 + (lane >> 2) + half * 8;
            int rr = rowBase + rloc;
            float ps = 0.f, pd = 0.f;
#pragma unroll
            for (int j = 0; j < NT; j++) {
                int cc = colBase + warp_n + j * 8 + (lane & 3) * 2;
                float v0 = acc[i][j][half * 2 + 0];
                float v1 = acc[i][j][half * 2 + 1];
                if (rr < M)
                    *(float2*)(Cm + (size_t)rr * Ntot + cc) = make_float2(v0, v1);
                float s0 = a_src[cc], s1 = a_src[cc + 1];
                float d0 = a_dst[cc], d1 = a_dst[cc + 1];
                ps += v0 * s0 + v1 * s1;
                pd += v0 * d0 + v1 * d1;
            }
            atomicAdd(&sals[rloc], ps);
            atomicAdd(&sald[rloc], pd);
        }
    }
    __syncthreads();
    if (tid < 128) {
        int gr = rowBase + tid;
        if (gr < M) {
            als[gr * HH + head] = sals[tid];
            ald[gr * HH + head] = sald[tid];
        }
    }
}

__device__ __forceinline__ float lrelu(float v) {
    return v > 0.f ? v : NEG_SLOPE * v;
}

// ----------------------------------------------------------------------------
// Fused layer-1 aggregation: single pass, shared per-edge weights (R14 winner).
// ----------------------------------------------------------------------------
__global__ __launch_bounds__(128) void agg1_kernel(
    const float* __restrict__ h, const float* __restrict__ als,
    const float* __restrict__ ald, const float* __restrict__ b1,
    const int* __restrict__ rowp, const int* __restrict__ csr_src,
    __nv_bfloat16* __restrict__ outs)
{
    const int n = blockIdx.x;
    const int tid = threadIdx.x;
    const int lane = tid & 31;
    const int hh = tid >> 5;

    __shared__ float sw[H][32];
    __shared__ int   ssrc[H][32];

    const int beg = rowp[n];
    const int end = rowp[n + 1];
    const float aldn = ald[n * H + hh];

    float dsum = 0.f;
    float4 acc = make_float4(0.f, 0.f, 0.f, 0.f);
    const float* hb = h + (size_t)tid * 4;

    for (int c = beg; c < end; c += 32) {
        int p = c + lane;
        float w = 0.f;
        int s = 0;
        if (p < end) {
            s = csr_src[p];
            w = __expf(lrelu(als[s * H + hh] + aldn));
            dsum += w;
        }
        sw[hh][lane] = w;
        ssrc[hh][lane] = s;
        __syncwarp();

        const int cnt = min(32, end - c);
        int j = 0;
        for (; j + 3 < cnt; j += 4) {
            float w0 = sw[hh][j],     w1 = sw[hh][j + 1];
            float w2 = sw[hh][j + 2], w3 = sw[hh][j + 3];
            int   s0 = ssrc[hh][j],     s1 = ssrc[hh][j + 1];
            int   s2 = ssrc[hh][j + 2], s3 = ssrc[hh][j + 3];
            float4 v0 = *(const float4*)(hb + (size_t)s0 * HID);
            float4 v1 = *(const float4*)(hb + (size_t)s1 * HID);
            float4 v2 = *(const float4*)(hb + (size_t)s2 * HID);
            float4 v3 = *(const float4*)(hb + (size_t)s3 * HID);
            acc.x = fmaf(v0.x, w0, acc.x); acc.y = fmaf(v0.y, w0, acc.y);
            acc.z = fmaf(v0.z, w0, acc.z); acc.w = fmaf(v0.w, w0, acc.w);
            acc.x = fmaf(v1.x, w1, acc.x); acc.y = fmaf(v1.y, w1, acc.y);
            acc.z = fmaf(v1.z, w1, acc.z); acc.w = fmaf(v1.w, w1, acc.w);
            acc.x = fmaf(v2.x, w2, acc.x); acc.y = fmaf(v2.y, w2, acc.y);
            acc.z = fmaf(v2.z, w2, acc.z); acc.w = fmaf(v2.w, w2, acc.w);
            acc.x = fmaf(v3.x, w3, acc.x); acc.y = fmaf(v3.y, w3, acc.y);
            acc.z = fmaf(v3.z, w3, acc.z); acc.w = fmaf(v3.w, w3, acc.w);
        }
        for (; j < cnt; j++) {
            float w0 = sw[hh][j];
            int   s0 = ssrc[hh][j];
            float4 v0 = *(const float4*)(hb + (size_t)s0 * HID);
            acc.x = fmaf(v0.x, w0, acc.x); acc.y = fmaf(v0.y, w0, acc.y);
            acc.z = fmaf(v0.z, w0, acc.z); acc.w = fmaf(v0.w, w0, acc.w);
        }
        __syncwarp();
    }

#pragma unroll
    for (int o = 16; o > 0; o >>= 1) dsum += __shfl_xor_sync(0xffffffffu, dsum, o);
    const float inv = 1.f / (dsum + 1e-16f);

    float4 bv = *(const float4*)(b1 + tid * 4);
    float vals[4] = { fmaf(acc.x, inv, bv.x), fmaf(acc.y, inv, bv.y),
                      fmaf(acc.z, inv, bv.z), fmaf(acc.w, inv, bv.w) };
    __nv_bfloat16* orow = outs + (size_t)n * K1;
#pragma unroll
    for (int j = 0; j < 4; j++) {
        float v = vals[j];
        v = v > 0.f ? v : expm1f(v);
        __nv_bfloat16 hi = __float2bfloat16(v);
        __nv_bfloat16 lo = __float2bfloat16(v - __bfloat162float(hi));
        int c2 = tid * 4 + j;
        orow[c2] = hi; orow[512 + c2] = lo;
    }
}

// ----------------------------------------------------------------------------
// Fused layer-2 aggregation: warp per dst node, chunked single pass.
// ----------------------------------------------------------------------------
__global__ __launch_bounds__(128) void agg2_kernel(
    const float* __restrict__ h, const float* __restrict__ als,
    const float* __restrict__ ald, const float* __restrict__ b2,
    const int* __restrict__ rowp, const int* __restrict__ csr_src,
    float* __restrict__ out)
{
    const int w4 = threadIdx.x >> 5;
    const int n = blockIdx.x * 4 + w4;
    if (n >= NN) return;
    const int lane = threadIdx.x & 31;

    __shared__ float sw[4][32];
    __shared__ int   ssrc[4][32];

    const int beg = rowp[n];
    const int end = rowp[n + 1];
    const float aldn = ald[n];

    float dsum = 0.f;
    float4 acc = make_float4(0.f, 0.f, 0.f, 0.f);
    const float* hb = h + (size_t)lane * 4;

    for (int c = beg; c < end; c += 32) {
        int p = c + lane;
        float w = 0.f;
        int s = 0;
        if (p < end) {
            s = csr_src[p];
            w = __expf(lrelu(als[s] + aldn));
            dsum += w;
        }
        sw[w4][lane] = w;
        ssrc[w4][lane] = s;
        __syncwarp();

        const int cnt = min(32, end - c);
        int j = 0;
        for (; j + 3 < cnt; j += 4) {
            float w0 = sw[w4][j],     w1 = sw[w4][j + 1];
            float w2 = sw[w4][j + 2], w3 = sw[w4][j + 3];
            int   s0 = ssrc[w4][j],     s1 = ssrc[w4][j + 1];
            int   s2 = ssrc[w4][j + 2], s3 = ssrc[w4][j + 3];
            float4 v0 = *(const float4*)(hb + (size_t)s0 * C);
            float4 v1 = *(const float4*)(hb + (size_t)s1 * C);
            float4 v2 = *(const float4*)(hb + (size_t)s2 * C);
            float4 v3 = *(const float4*)(hb + (size_t)s3 * C);
            acc.x = fmaf(v0.x, w0, acc.x); acc.y = fmaf(v0.y, w0, acc.y);
            acc.z = fmaf(v0.z, w0, acc.z); acc.w = fmaf(v0.w, w0, acc.w);
            acc.x = fmaf(v1.x, w1, acc.x); acc.y = fmaf(v1.y, w1, acc.y);
            acc.z = fmaf(v1.z, w1, acc.z); acc.w = fmaf(v1.w, w1, acc.w);
            acc.x = fmaf(v2.x, w2, acc.x); acc.y = fmaf(v2.y, w2, acc.y);
            acc.z = fmaf(v2.z, w2, acc.z); acc.w = fmaf(v2.w, w2, acc.w);
            acc.x = fmaf(v3.x, w3, acc.x); acc.y = fmaf(v3.y, w3, acc.y);
            acc.z = fmaf(v3.z, w3, acc.z); acc.w = fmaf(v3.w, w3, acc.w);
        }
        for (; j < cnt; j++) {
            float w0 = sw[w4][j];
            int   s0 = ssrc[w4][j];
            float4 v0 = *(const float4*)(hb + (size_t)s0 * C);
            acc.x = fmaf(v0.x, w0, acc.x); acc.y = fmaf(v0.y, w0, acc.y);
            acc.z = fmaf(v0.z, w0, acc.z); acc.w = fmaf(v0.w, w0, acc.w);
        }
        __syncwarp();
    }

#pragma unroll
    for (int o = 16; o > 0; o >>= 1) dsum += __shfl_xor_sync(0xffffffffu, dsum, o);
    const float inv = 1.f / (dsum + 1e-16f);

    float4 bv = *(const float4*)(b2 + lane * 4);
    float4 r = make_float4(fmaf(acc.x, inv, bv.x), fmaf(acc.y, inv, bv.y),
                           fmaf(acc.z, inv, bv.z), fmaf(acc.w, inv, bv.w));
    *(float4*)(out + (size_t)n * C + lane * 4) = r;
}

// ----------------------------------------------------------------------------
// Launch: edge chain + conv_w2 forked onto a second stream.
// ----------------------------------------------------------------------------
extern "C" void kernel_launch(void* const* d_in, const int* in_sizes, int n_in,
                              void* d_out, int out_size)
{
    const float* x      = (const float*)d_in[0];
    const void*  ei     = d_in[1];
    const float* W1     = (const float*)d_in[2];
    const float* a_src1 = (const float*)d_in[3];
    const float* a_dst1 = (const float*)d_in[4];
    const float* b1     = (const float*)d_in[5];
    const float* W2     = (const float*)d_in[6];
    const float* a_src2 = (const float*)d_in[7];
    const float* a_dst2 = (const float*)d_in[8];
    const float* b2     = (const float*)d_in[9];
    float*       out    = (float*)d_out;

    __nv_bfloat16 *xs, *w1t, *w2t, *out1s;
    float *h1, *h2, *als1, *ald1, *als2, *ald2;
    int *src, *dst, *deg, *rowp, *cursor, *csr_src, *bsum, *boff;
    cudaGetSymbolAddress((void**)&xs,      g_xs);
    cudaGetSymbolAddress((void**)&w1t,     g_w1t);
    cudaGetSymbolAddress((void**)&w2t,     g_w2t);
    cudaGetSymbolAddress((void**)&out1s,   g_out1s);
    cudaGetSymbolAddress((void**)&h1,      g_h1);
    cudaGetSymbolAddress((void**)&h2,      g_h2);
    cudaGetSymbolAddress((void**)&als1,    g_als1);
    cudaGetSymbolAddress((void**)&ald1,    g_ald1);
    cudaGetSymbolAddress((void**)&als2,    g_als2);
    cudaGetSymbolAddress((void**)&ald2,    g_ald2);
    cudaGetSymbolAddress((void**)&src,     g_src);
    cudaGetSymbolAddress((void**)&dst,     g_dst);
    cudaGetSymbolAddress((void**)&deg,     g_deg);
    cudaGetSymbolAddress((void**)&rowp,    g_rowp);
    cudaGetSymbolAddress((void**)&cursor,  g_cursor);
    cudaGetSymbolAddress((void**)&csr_src, g_csr_src);
    cudaGetSymbolAddress((void**)&bsum,    g_bsum);
    cudaGetSymbolAddress((void**)&boff,    g_boff);

    static cudaStream_t s2 = nullptr;
    static cudaEvent_t e_fork = nullptr, e_join = nullptr;
    if (s2 == nullptr) {
        cudaStreamCreateWithFlags(&s2, cudaStreamNonBlocking);
        cudaEventCreateWithFlags(&e_fork, cudaEventDisableTiming);
        cudaEventCreateWithFlags(&e_join, cudaEventDisableTiming);
        cudaFuncSetAttribute(hmma_gemm_attn_kernel,
                             cudaFuncAttributeMaxDynamicSharedMemorySize, SMEM_G);
    }

    // ---- fork: edge decode + CSR build + conv_w2 on s2 ----
    cudaEventRecord(e_fork, 0);
    cudaStreamWaitEvent(s2, e_fork, 0);
    zero_init_kernel<<<(NN + 255) / 256, 256, 0, s2>>>(deg, NN);
    det_kernel<<<256, 256, 0, s2>>>((const long long*)ei);
    prep_edges_kernel<<<(ET + 255) / 256, 256, 0, s2>>>(ei, src, dst, deg);
    scan1_kernel<<<SCAN_NB, SCAN_B, 0, s2>>>(deg, rowp, bsum);
    scan2_kernel<<<1, 64, 0, s2>>>(bsum, boff);
    scan3_kernel<<<(NN + 255) / 256, 256, 0, s2>>>(rowp, boff, cursor);
    scatter_kernel<<<(ET + 255) / 256, 256, 0, s2>>>(src, dst, cursor, csr_src);
    conv_w_kernel<<<(512 * C + 255) / 256, 256, 0, s2>>>(W2, w2t, C);
    cudaEventRecord(e_join, s2);

    // ---- main stream: conversions + GEMM1 ----
    conv_x_kernel<<<(NN * 128 + 255) / 256, 256>>>(x, xs);
    conv_w_kernel<<<(512 * HID + 255) / 256, 256>>>(W1, w1t, HID);
    {
        dim3 grid(HID / 128, (NN + 127) / 128);   // (4, 157)
        hmma_gemm_attn_kernel<<<grid, 256, SMEM_G>>>(xs, w1t, h1, NN, HID,
                                                     a_src1, a_dst1, als1, ald1, H);
    }

    // ---- join: agg1 needs CSR + GEMM1 ----
    cudaStreamWaitEvent(0, e_join, 0);
    agg1_kernel<<<NN, 128>>>(h1, als1, ald1, b1, rowp, csr_src, out1s);

    // ---- layer 2 ----
    {
        dim3 grid(1, (NN + 127) / 128);           // (1, 157)
        hmma_gemm_attn_kernel<<<grid, 256, SMEM_G>>>(out1s, w2t, h2, NN, C,
                                                     a_src2, a_dst2, als2, ald2, 1);
    }
    agg2_kernel<<<(NN + 3) / 4, 128>>>(h2, als2, ald2, b2, rowp, csr_src, out);
}

// round 17
// speedup vs baseline: 1.1840x; 1.1840x over previous
#include <cuda_runtime.h>
#include <cuda_bf16.h>
#include <cuda_fp16.h>
#include <math.h>
#include <stdint.h>

// Problem constants
constexpr int NN   = 20000;
constexpr int INC  = 512;
constexpr int C    = 128;
constexpr int H    = 4;
constexpr int HID  = H * C;        // 512
constexpr int NE   = 320000;
constexpr int ET   = NE + NN;      // 340000
constexpr int K1   = 1024;         // [hi|lo] split storage width
constexpr float NEG_SLOPE = 0.2f;
constexpr int SCAN_B = 512;
constexpr int SCAN_NB = (NN + SCAN_B - 1) / SCAN_B;  // 40

// ----------------------------------------------------------------------------
// Device-global scratch
// ----------------------------------------------------------------------------
__device__ __nv_bfloat16 g_xs[(size_t)NN * K1];
__device__ __nv_bfloat16 g_w1t[(size_t)HID * K1];
__device__ __nv_bfloat16 g_w2t[(size_t)C * K1];
__device__ __half g_h1[(size_t)NN * HID];           // x @ W1 (fp16: agg1-only consumer)
__device__ __nv_bfloat16 g_out1s[(size_t)NN * K1];
__device__ float g_h2[(size_t)NN * C];
__device__ float g_als1[NN * H];
__device__ float g_ald1[NN * H];
__device__ float g_als2[NN];
__device__ float g_ald2[NN];
__device__ int   g_src[ET];
__device__ int   g_dst[ET];
__device__ int   g_deg[NN];
__device__ int   g_rowp[NN + 1];
__device__ int   g_cursor[NN];
__device__ int   g_csr_src[ET];
__device__ int   g_bsum[SCAN_NB];
__device__ int   g_boff[SCAN_NB];
__device__ int   g_is64;

// ----------------------------------------------------------------------------
// Edge-index dtype probe + decode + CSR build
// ----------------------------------------------------------------------------
__global__ void zero_init_kernel(int* __restrict__ p, int n) {
    int i = blockIdx.x * blockDim.x + threadIdx.x;
    if (i < n) p[i] = 0;
    if (i == 0) g_is64 = 1;
}
__global__ void det_kernel(const long long* __restrict__ p) {
    int i = blockIdx.x * blockDim.x + threadIdx.x;
    if (i < 65536) {
        unsigned long long v = (unsigned long long)p[i];
        if (v >= (unsigned long long)NN) g_is64 = 0;
    }
}
__global__ void prep_edges_kernel(const void* __restrict__ eib,
                                  int* __restrict__ src, int* __restrict__ dst,
                                  int* __restrict__ deg) {
    int e = blockIdx.x * blockDim.x + threadIdx.x;
    if (e >= ET) return;
    int s, d;
    if (e < NE) {
        if (g_is64) {
            const long long* p = (const long long*)eib;
            s = (int)p[e]; d = (int)p[NE + e];
        } else {
            const int* p = (const int*)eib;
            s = p[e]; d = p[NE + e];
        }
    } else {
        s = d = e - NE;
    }
    src[e] = s; dst[e] = d;
    atomicAdd(&deg[d], 1);
}
__global__ __launch_bounds__(SCAN_B) void scan1_kernel(const int* __restrict__ deg,
                                                       int* __restrict__ rowp,
                                                       int* __restrict__ bsum) {
    __shared__ int sh[SCAN_B];
    const int t = threadIdx.x;
    const int i = blockIdx.x * SCAN_B + t;
    int v = (i < NN) ? deg[i] : 0;
    sh[t] = v;
    __syncthreads();
    for (int off = 1; off < SCAN_B; off <<= 1) {
        int u = (t >= off) ? sh[t - off] : 0;
        __syncthreads();
        sh[t] += u;
        __syncthreads();
    }
    if (i < NN) rowp[i] = sh[t] - v;
    if (t == SCAN_B - 1) bsum[blockIdx.x] = sh[t];
}
__global__ void scan2_kernel(const int* __restrict__ bsum, int* __restrict__ boff) {
    int t = threadIdx.x;   // 64
    __shared__ int sh[64];
    sh[t] = (t < SCAN_NB) ? bsum[t] : 0;
    __syncthreads();
    for (int off = 1; off < 64; off <<= 1) {
        int u = (t >= off) ? sh[t - off] : 0;
        __syncthreads();
        sh[t] += u;
        __syncthreads();
    }
    if (t < SCAN_NB) boff[t] = sh[t] - bsum[t];
}
__global__ void scan3_kernel(int* __restrict__ rowp, const int* __restrict__ boff,
                             int* __restrict__ cursor) {
    int i = blockIdx.x * blockDim.x + threadIdx.x;
    if (i < NN) {
        int r = rowp[i] + boff[i / SCAN_B];
        rowp[i] = r;
        cursor[i] = r;
    }
    if (i == 0) rowp[NN] = ET;
}
__global__ void scatter_kernel(const int* __restrict__ src, const int* __restrict__ dst,
                               int* __restrict__ cursor, int* __restrict__ csr_src) {
    int e = blockIdx.x * blockDim.x + threadIdx.x;
    if (e >= ET) return;
    int p = atomicAdd(&cursor[dst[e]], 1);
    csr_src[p] = src[e];
}

// ----------------------------------------------------------------------------
// fp32 -> bf16 [hi|lo] split conversions (K1 = 1024 layout).
// ----------------------------------------------------------------------------
__global__ void conv_x_kernel(const float* __restrict__ x, __nv_bfloat16* __restrict__ xs) {
    int idx = blockIdx.x * blockDim.x + threadIdx.x;
    if (idx >= NN * 128) return;
    int row = idx >> 7, q = idx & 127;
    float4 v = *(const float4*)(x + (size_t)row * 512 + q * 4);
    __nv_bfloat16* o = xs + (size_t)row * K1 + q * 4;
    float vals[4] = { v.x, v.y, v.z, v.w };
#pragma unroll
    for (int j = 0; j < 4; j++) {
        __nv_bfloat16 hi = __float2bfloat16(vals[j]);
        __nv_bfloat16 lo = __float2bfloat16(vals[j] - __bfloat162float(hi));
        o[j] = hi; o[512 + j] = lo;
    }
}
__global__ void conv_w_kernel(const float* __restrict__ W, __nv_bfloat16* __restrict__ wt, int N) {
    int idx = blockIdx.x * blockDim.x + threadIdx.x;
    if (idx >= 512 * N) return;
    int k = idx / N, n = idx % N;
    float v = W[(size_t)k * N + n];
    __nv_bfloat16 hi = __float2bfloat16(v);
    __nv_bfloat16 lo = __float2bfloat16(v - __bfloat162float(hi));
    __nv_bfloat16* o = wt + (size_t)n * K1;
    o[k] = hi; o[512 + k] = lo;
}

// ----------------------------------------------------------------------------
// HMMA GEMM + fused attention epilogue (R15 proven structure: GK=64, 24 iters).
// half_out: C written as fp16 (layer 1 -> agg1) or fp32 (layer 2).
// Attention dots always computed from exact fp32 accumulators.
// ----------------------------------------------------------------------------
constexpr int GK     = 64;
constexpr int LDT    = 72;                 // padded SMEM stride (bf16), 144 B
constexpr int NCHT   = 24;                 // 3 terms x 8 chunks
constexpr int NT     = 4;
constexpr int TILESZ = 128 * LDT * 2;      // 18432 B
constexpr int SMEM_G = 2 * 2 * TILESZ;     // 73728

__device__ __forceinline__ uint32_t smem_u32(const void* p) {
    uint32_t a;
    asm("{ .reg .u64 t; cvta.to.shared.u64 t, %1; cvt.u32.u64 %0, t; }"
        : "=r"(a) : "l"(p));
    return a;
}
__device__ __forceinline__ void cp16(uint32_t dst, const void* src, uint32_t sz) {
    asm volatile("cp.async.ca.shared.global [%0], [%1], 16, %2;"
                 :: "r"(dst), "l"(src), "r"(sz));
}
__device__ __forceinline__ void ldm_x4(uint32_t* r, uint32_t addr) {
    asm volatile("ldmatrix.sync.aligned.m8n8.x4.shared.b16 {%0,%1,%2,%3}, [%4];"
                 : "=r"(r[0]), "=r"(r[1]), "=r"(r[2]), "=r"(r[3]) : "r"(addr));
}
__device__ __forceinline__ void mma16816(float* d, const uint32_t* a, const uint32_t* b) {
    asm volatile(
        "mma.sync.aligned.m16n8k16.row.col.f32.bf16.bf16.f32 "
        "{%0,%1,%2,%3}, {%4,%5,%6,%7}, {%8,%9}, {%0,%1,%2,%3};"
        : "+f"(d[0]), "+f"(d[1]), "+f"(d[2]), "+f"(d[3])
        : "r"(a[0]), "r"(a[1]), "r"(a[2]), "r"(a[3]), "r"(b[0]), "r"(b[1]));
}

__global__ __launch_bounds__(256) void hmma_gemm_attn_kernel(
    const __nv_bfloat16* __restrict__ A, const __nv_bfloat16* __restrict__ B,
    void* __restrict__ Cm, int M, int Ntot, int half_out,
    const float* __restrict__ a_src, const float* __restrict__ a_dst,
    float* __restrict__ als, float* __restrict__ ald, int HH)
{
    extern __shared__ __align__(128) char smem[];
    __shared__ float sals[128];
    __shared__ float sald[128];
    const uint32_t sbase = smem_u32(smem);

    const int tid  = threadIdx.x;
    const int wid  = tid >> 5;
    const int lane = tid & 31;
    const int warp_m = (wid >> 2) * 64;
    const int warp_n = (wid & 3) * 32;
    const int rowBase = blockIdx.y * 128;
    const int colBase = blockIdx.x * 128;
    const int head = blockIdx.x;

    if (tid < 128) { sals[tid] = 0.f; sald[tid] = 0.f; }

    float acc[4][NT][4];
#pragma unroll
    for (int i = 0; i < 4; i++)
#pragma unroll
        for (int j = 0; j < NT; j++)
#pragma unroll
            for (int q = 0; q < 4; q++) acc[i][j][q] = 0.f;

    auto prefetch = [&](int ch, int buf) {
        const int term = ch >> 3;        // 0..2
        const int kk   = ch & 7;         // 0..7
        const int aoff = (term == 2) ? 512 : 0;
        const int boff = (term == 1) ? 512 : 0;
        uint32_t ab = sbase + buf * 2 * TILESZ;
        uint32_t bb = ab + TILESZ;
        const __nv_bfloat16* Ac = A + aoff + kk * GK;
        const __nv_bfloat16* Bc = B + boff + kk * GK;
#pragma unroll
        for (int i = tid; i < 1024; i += 256) {   // 128 rows x 8 16B-chunks
            int row = i >> 3, c16 = i & 7;
            uint32_t off = row * (LDT * 2) + c16 * 16;
            cp16(ab + off, Ac + (size_t)(rowBase + row) * K1 + c16 * 8,
                 (rowBase + row < M) ? 16u : 0u);
            cp16(bb + off, Bc + (size_t)(colBase + row) * K1 + c16 * 8, 16u);
        }
        asm volatile("cp.async.commit_group;");
    };

    prefetch(0, 0);

    for (int ch = 0; ch < NCHT; ch++) {
        const int buf = ch & 1;
        if (ch + 1 < NCHT) {
            prefetch(ch + 1, buf ^ 1);
            asm volatile("cp.async.wait_group 1;");
        } else {
            asm volatile("cp.async.wait_group 0;");
        }
        __syncthreads();

        uint32_t ab = sbase + buf * 2 * TILESZ;
        uint32_t bb = ab + TILESZ;

#pragma unroll
        for (int ks = 0; ks < 4; ks++) {
            uint32_t afrag[4][4];
#pragma unroll
            for (int i = 0; i < 4; i++) {
                int row = warp_m + i * 16 + (lane & 15);
                int col = ks * 16 + ((lane >> 4) << 3);
                ldm_x4(afrag[i], ab + row * (LDT * 2) + col * 2);
            }
            uint32_t bfrag[NT][2];
#pragma unroll
            for (int jj = 0; jj < NT / 2; jj++) {
                uint32_t r[4];
                int nrow = warp_n + jj * 16 + (lane & 7) + ((lane >> 4) << 3);
                int col  = ks * 16 + (((lane >> 3) & 1) << 3);
                ldm_x4(r, bb + nrow * (LDT * 2) + col * 2);
                bfrag[2 * jj + 0][0] = r[0]; bfrag[2 * jj + 0][1] = r[1];
                bfrag[2 * jj + 1][0] = r[2]; bfrag[2 * jj + 1][1] = r[3];
            }
#pragma unroll
            for (int i = 0; i < 4; i++)
#pragma unroll
                for (int j = 0; j < NT; j++)
                    mma16816(acc[i][j], afrag[i], bfrag[j]);
        }
        __syncthreads();
    }

    // Epilogue: store C tile (fp16 or fp32) + reduce attention dots into smem.
#pragma unroll
    for (int i = 0; i < 4; i++) {
#pragma unroll
        for (int half = 0; half < 2; half++) {
            int rloc = warp_m + i * 16 + (lane >> 2) + half * 8;
            int rr = rowBase + rloc;
            float ps = 0.f, pd = 0.f;
#pragma unroll
            for (int j = 0; j < NT; j++) {
                int cc = colBase + warp_n + j * 8 + (lane & 3) * 2;
                float v0 = acc[i][j][half * 2 + 0];
                float v1 = acc[i][j][half * 2 + 1];
                if (rr < M) {
                    if (half_out) {
                        __half2 hv = __floats2half2_rn(v0, v1);
                        *(__half2*)((__half*)Cm + (size_t)rr * Ntot + cc) = hv;
                    } else {
                        *(float2*)((float*)Cm + (size_t)rr * Ntot + cc) = make_float2(v0, v1);
                    }
                }
                float s0 = a_src[cc], s1 = a_src[cc + 1];
                float d0 = a_dst[cc], d1 = a_dst[cc + 1];
                ps += v0 * s0 + v1 * s1;
                pd += v0 * d0 + v1 * d1;
            }
            atomicAdd(&sals[rloc], ps);
            atomicAdd(&sald[rloc], pd);
        }
    }
    __syncthreads();
    if (tid < 128) {
        int gr = rowBase + tid;
        if (gr < M) {
            als[gr * HH + head] = sals[tid];
            ald[gr * HH + head] = sald[tid];
        }
    }
}

__device__ __forceinline__ float lrelu(float v) {
    return v > 0.f ? v : NEG_SLOPE * v;
}

// ----------------------------------------------------------------------------
// Fused layer-1 aggregation: fp16 h1 gather (half traffic), shared per-edge
// weights, unnormalized accumulation + final normalize, ELU + bf16 split out.
// ----------------------------------------------------------------------------
__device__ __forceinline__ void acc_half4(float4& acc, const __half* p, float w) {
    uint2 raw = *(const uint2*)p;
    __half2 h01 = *(__half2*)&raw.x;
    __half2 h23 = *(__half2*)&raw.y;
    float2 f01 = __half22float2(h01);
    float2 f23 = __half22float2(h23);
    acc.x = fmaf(f01.x, w, acc.x);
    acc.y = fmaf(f01.y, w, acc.y);
    acc.z = fmaf(f23.x, w, acc.z);
    acc.w = fmaf(f23.y, w, acc.w);
}

__global__ __launch_bounds__(128) void agg1_kernel(
    const __half* __restrict__ h, const float* __restrict__ als,
    const float* __restrict__ ald, const float* __restrict__ b1,
    const int* __restrict__ rowp, const int* __restrict__ csr_src,
    __nv_bfloat16* __restrict__ outs)
{
    const int n = blockIdx.x;
    const int tid = threadIdx.x;
    const int lane = tid & 31;
    const int hh = tid >> 5;

    __shared__ float sw[H][32];
    __shared__ int   ssrc[H][32];

    const int beg = rowp[n];
    const int end = rowp[n + 1];
    const float aldn = ald[n * H + hh];

    float dsum = 0.f;
    float4 acc = make_float4(0.f, 0.f, 0.f, 0.f);
    const __half* hb = h + (size_t)tid * 4;

    for (int c = beg; c < end; c += 32) {
        int p = c + lane;
        float w = 0.f;
        int s = 0;
        if (p < end) {
            s = csr_src[p];
            w = __expf(lrelu(als[s * H + hh] + aldn));
            dsum += w;
        }
        sw[hh][lane] = w;
        ssrc[hh][lane] = s;
        __syncwarp();

        const int cnt = min(32, end - c);
        int j = 0;
        for (; j + 3 < cnt; j += 4) {
            float w0 = sw[hh][j],     w1 = sw[hh][j + 1];
            float w2 = sw[hh][j + 2], w3 = sw[hh][j + 3];
            int   s0 = ssrc[hh][j],     s1 = ssrc[hh][j + 1];
            int   s2 = ssrc[hh][j + 2], s3 = ssrc[hh][j + 3];
            acc_half4(acc, hb + (size_t)s0 * HID, w0);
            acc_half4(acc, hb + (size_t)s1 * HID, w1);
            acc_half4(acc, hb + (size_t)s2 * HID, w2);
            acc_half4(acc, hb + (size_t)s3 * HID, w3);
        }
        for (; j < cnt; j++) {
            acc_half4(acc, hb + (size_t)ssrc[hh][j] * HID, sw[hh][j]);
        }
        __syncwarp();
    }

#pragma unroll
    for (int o = 16; o > 0; o >>= 1) dsum += __shfl_xor_sync(0xffffffffu, dsum, o);
    const float inv = 1.f / (dsum + 1e-16f);

    float4 bv = *(const float4*)(b1 + tid * 4);
    float vals[4] = { fmaf(acc.x, inv, bv.x), fmaf(acc.y, inv, bv.y),
                      fmaf(acc.z, inv, bv.z), fmaf(acc.w, inv, bv.w) };
    __nv_bfloat16* orow = outs + (size_t)n * K1;
#pragma unroll
    for (int j = 0; j < 4; j++) {
        float v = vals[j];
        v = v > 0.f ? v : expm1f(v);
        __nv_bfloat16 hi = __float2bfloat16(v);
        __nv_bfloat16 lo = __float2bfloat16(v - __bfloat162float(hi));
        int c2 = tid * 4 + j;
        orow[c2] = hi; orow[512 + c2] = lo;
    }
}

// ----------------------------------------------------------------------------
// Fused layer-2 aggregation: warp per dst node, chunked single pass (fp32 h2).
// ----------------------------------------------------------------------------
__global__ __launch_bounds__(128) void agg2_kernel(
    const float* __restrict__ h, const float* __restrict__ als,
    const float* __restrict__ ald, const float* __restrict__ b2,
    const int* __restrict__ rowp, const int* __restrict__ csr_src,
    float* __restrict__ out)
{
    const int w4 = threadIdx.x >> 5;
    const int n = blockIdx.x * 4 + w4;
    if (n >= NN) return;
    const int lane = threadIdx.x & 31;

    __shared__ float sw[4][32];
    __shared__ int   ssrc[4][32];

    const int beg = rowp[n];
    const int end = rowp[n + 1];
    const float aldn = ald[n];

    float dsum = 0.f;
    float4 acc = make_float4(0.f, 0.f, 0.f, 0.f);
    const float* hb = h + (size_t)lane * 4;

    for (int c = beg; c < end; c += 32) {
        int p = c + lane;
        float w = 0.f;
        int s = 0;
        if (p < end) {
            s = csr_src[p];
            w = __expf(lrelu(als[s] + aldn));
            dsum += w;
        }
        sw[w4][lane] = w;
        ssrc[w4][lane] = s;
        __syncwarp();

        const int cnt = min(32, end - c);
        int j = 0;
        for (; j + 3 < cnt; j += 4) {
            float w0 = sw[w4][j],     w1 = sw[w4][j + 1];
            float w2 = sw[w4][j + 2], w3 = sw[w4][j + 3];
            int   s0 = ssrc[w4][j],     s1 = ssrc[w4][j + 1];
            int   s2 = ssrc[w4][j + 2], s3 = ssrc[w4][j + 3];
            float4 v0 = *(const float4*)(hb + (size_t)s0 * C);
            float4 v1 = *(const float4*)(hb + (size_t)s1 * C);
            float4 v2 = *(const float4*)(hb + (size_t)s2 * C);
            float4 v3 = *(const float4*)(hb + (size_t)s3 * C);
            acc.x = fmaf(v0.x, w0, acc.x); acc.y = fmaf(v0.y, w0, acc.y);
            acc.z = fmaf(v0.z, w0, acc.z); acc.w = fmaf(v0.w, w0, acc.w);
            acc.x = fmaf(v1.x, w1, acc.x); acc.y = fmaf(v1.y, w1, acc.y);
            acc.z = fmaf(v1.z, w1, acc.z); acc.w = fmaf(v1.w, w1, acc.w);
            acc.x = fmaf(v2.x, w2, acc.x); acc.y = fmaf(v2.y, w2, acc.y);
            acc.z = fmaf(v2.z, w2, acc.z); acc.w = fmaf(v2.w, w2, acc.w);
            acc.x = fmaf(v3.x, w3, acc.x); acc.y = fmaf(v3.y, w3, acc.y);
            acc.z = fmaf(v3.z, w3, acc.z); acc.w = fmaf(v3.w, w3, acc.w);
        }
        for (; j < cnt; j++) {
            float w0 = sw[w4][j];
            int   s0 = ssrc[w4][j];
            float4 v0 = *(const float4*)(hb + (size_t)s0 * C);
            acc.x = fmaf(v0.x, w0, acc.x); acc.y = fmaf(v0.y, w0, acc.y);
            acc.z = fmaf(v0.z, w0, acc.z); acc.w = fmaf(v0.w, w0, acc.w);
        }
        __syncwarp();
    }

#pragma unroll
    for (int o = 16; o > 0; o >>= 1) dsum += __shfl_xor_sync(0xffffffffu, dsum, o);
    const float inv = 1.f / (dsum + 1e-16f);

    float4 bv = *(const float4*)(b2 + lane * 4);
    float4 r = make_float4(fmaf(acc.x, inv, bv.x), fmaf(acc.y, inv, bv.y),
                           fmaf(acc.z, inv, bv.z), fmaf(acc.w, inv, bv.w));
    *(float4*)(out + (size_t)n * C + lane * 4) = r;
}

// ----------------------------------------------------------------------------
// Launch: edge chain + conv_w2 forked onto a second stream.
// ----------------------------------------------------------------------------
extern "C" void kernel_launch(void* const* d_in, const int* in_sizes, int n_in,
                              void* d_out, int out_size)
{
    const float* x      = (const float*)d_in[0];
    const void*  ei     = d_in[1];
    const float* W1     = (const float*)d_in[2];
    const float* a_src1 = (const float*)d_in[3];
    const float* a_dst1 = (const float*)d_in[4];
    const float* b1     = (const float*)d_in[5];
    const float* W2     = (const float*)d_in[6];
    const float* a_src2 = (const float*)d_in[7];
    const float* a_dst2 = (const float*)d_in[8];
    const float* b2     = (const float*)d_in[9];
    float*       out    = (float*)d_out;

    __nv_bfloat16 *xs, *w1t, *w2t, *out1s;
    __half *h1;
    float *h2, *als1, *ald1, *als2, *ald2;
    int *src, *dst, *deg, *rowp, *cursor, *csr_src, *bsum, *boff;
    cudaGetSymbolAddress((void**)&xs,      g_xs);
    cudaGetSymbolAddress((void**)&w1t,     g_w1t);
    cudaGetSymbolAddress((void**)&w2t,     g_w2t);
    cudaGetSymbolAddress((void**)&out1s,   g_out1s);
    cudaGetSymbolAddress((void**)&h1,      g_h1);
    cudaGetSymbolAddress((void**)&h2,      g_h2);
    cudaGetSymbolAddress((void**)&als1,    g_als1);
    cudaGetSymbolAddress((void**)&ald1,    g_ald1);
    cudaGetSymbolAddress((void**)&als2,    g_als2);
    cudaGetSymbolAddress((void**)&ald2,    g_ald2);
    cudaGetSymbolAddress((void**)&src,     g_src);
    cudaGetSymbolAddress((void**)&dst,     g_dst);
    cudaGetSymbolAddress((void**)&deg,     g_deg);
    cudaGetSymbolAddress((void**)&rowp,    g_rowp);
    cudaGetSymbolAddress((void**)&cursor,  g_cursor);
    cudaGetSymbolAddress((void**)&csr_src, g_csr_src);
    cudaGetSymbolAddress((void**)&bsum,    g_bsum);
    cudaGetSymbolAddress((void**)&boff,    g_boff);

    static cudaStream_t s2 = nullptr;
    static cudaEvent_t e_fork = nullptr, e_join = nullptr;
    if (s2 == nullptr) {
        cudaStreamCreateWithFlags(&s2, cudaStreamNonBlocking);
        cudaEventCreateWithFlags(&e_fork, cudaEventDisableTiming);
        cudaEventCreateWithFlags(&e_join, cudaEventDisableTiming);
        cudaFuncSetAttribute(hmma_gemm_attn_kernel,
                             cudaFuncAttributeMaxDynamicSharedMemorySize, SMEM_G);
    }

    // ---- fork: edge decode + CSR build + conv_w2 on s2 ----
    cudaEventRecord(e_fork, 0);
    cudaStreamWaitEvent(s2, e_fork, 0);
    zero_init_kernel<<<(NN + 255) / 256, 256, 0, s2>>>(deg, NN);
    det_kernel<<<256, 256, 0, s2>>>((const long long*)ei);
    prep_edges_kernel<<<(ET + 255) / 256, 256, 0, s2>>>(ei, src, dst, deg);
    scan1_kernel<<<SCAN_NB, SCAN_B, 0, s2>>>(deg, rowp, bsum);
    scan2_kernel<<<1, 64, 0, s2>>>(bsum, boff);
    scan3_kernel<<<(NN + 255) / 256, 256, 0, s2>>>(rowp, boff, cursor);
    scatter_kernel<<<(ET + 255) / 256, 256, 0, s2>>>(src, dst, cursor, csr_src);
    conv_w_kernel<<<(512 * C + 255) / 256, 256, 0, s2>>>(W2, w2t, C);
    cudaEventRecord(e_join, s2);

    // ---- main stream: conversions + GEMM1 ----
    conv_x_kernel<<<(NN * 128 + 255) / 256, 256>>>(x, xs);
    conv_w_kernel<<<(512 * HID + 255) / 256, 256>>>(W1, w1t, HID);
    {
        dim3 grid(HID / 128, (NN + 127) / 128);   // (4, 157)
        hmma_gemm_attn_kernel<<<grid, 256, SMEM_G>>>(xs, w1t, h1, NN, HID, 1,
                                                     a_src1, a_dst1, als1, ald1, H);
    }

    // ---- join: agg1 needs CSR + GEMM1 ----
    cudaStreamWaitEvent(0, e_join, 0);
    agg1_kernel<<<NN, 128>>>(h1, als1, ald1, b1, rowp, csr_src, out1s);

    // ---- layer 2 ----
    {
        dim3 grid(1, (NN + 127) / 128);           // (1, 157)
        hmma_gemm_attn_kernel<<<grid, 256, SMEM_G>>>(out1s, w2t, h2, NN, C, 0,
                                                     a_src2, a_dst2, als2, ald2, 1);
    }
    agg2_kernel<<<(NN + 3) / 4, 128>>>(h2, als2, ald2, b2, rowp, csr_src, out);
}